// round 5
// baseline (speedup 1.0000x reference)
#include <cuda_runtime.h>
#include <math.h>
#include <stdint.h>

// Problem constants
#define B_  32
#define C_  512
#define M_  784            // 28*28
#define NSQ (C_*C_)        // 262144

// ---------------- scratch ----------------
__device__ float g_A [B_*NSQ];   // covariance matrices
__device__ float g_mean[B_*C_];
__device__ float g_itr[B_];      // 1/trace
__device__ float g_str[B_];      // sqrt(trace)
__device__ float g_cs [B_*C_];   // final column means

// ================= warp-level tf32 MMA (sm_80 ISA) =================
__device__ __forceinline__ void mma_tf32(float* c, const uint32_t* a, const uint32_t* b) {
    asm volatile("mma.sync.aligned.m16n8k8.row.col.f32.tf32.tf32.f32 "
        "{%0,%1,%2,%3}, {%4,%5,%6,%7}, {%8,%9}, {%0,%1,%2,%3};"
        : "+f"(c[0]), "+f"(c[1]), "+f"(c[2]), "+f"(c[3])
        : "r"(a[0]), "r"(a[1]), "r"(a[2]), "r"(a[3]), "r"(b[0]), "r"(b[1]));
}
#define HI_MASK 0xFFFFE000u
__device__ __forceinline__ void split_tf32(float x, uint32_t& hi, uint32_t& lo) {
    uint32_t xb = __float_as_uint(x);
    hi = xb & HI_MASK;
    float lof = x - __uint_as_float(hi);
    lo = __float_as_uint(lof) & HI_MASK;
}

// ================= covariance GEMM (symmetric, upper-tri tiles only) =================
#define KCH  32
#define GT   256
#define APAD 36
#define ATILE_F (128*APAD)
#define STAGE_F (2*ATILE_F)
#define GEMM_SMEM (2*STAGE_F*4)   // 73728 bytes

__constant__ int c_bi[10] = {0,0,0,0,1,1,1,2,2,3};
__constant__ int c_bj[10] = {0,1,2,3,1,2,3,2,3,3};

__global__ void __launch_bounds__(GT)
cov_gemm(const float* __restrict__ xg, float* __restrict__ Cg,
         const float* __restrict__ meang)
{
    extern __shared__ float sm[];
    const int tid = threadIdx.x;
    const int b = blockIdx.z;
    const float* A  = xg + (long)b * C_ * M_;
    float*       C  = Cg + (long)b * NSQ;
    const int ib = c_bi[blockIdx.x] * 128;
    const int jb = c_bj[blockIdx.x] * 128;
    const int K = M_;
    const float covInvM = 1.0f / M_;

    const int wid = tid >> 5, lane = tid & 31;
    const int wm = wid & 1, wn = wid >> 1;
    const int gid = lane >> 2, tig = lane & 3;

    float acc[4][4][4];
    #pragma unroll
    for (int mf = 0; mf < 4; mf++)
        #pragma unroll
        for (int nf = 0; nf < 4; nf++)
            #pragma unroll
            for (int e = 0; e < 4; e++) acc[mf][nf][e] = 0.f;

    const int NC = (K + KCH - 1) / KCH;
    float4 ra[4], rb[4];

    #pragma unroll
    for (int q = 0; q < 4; q++) {
        int f = tid + q * GT; int r = f >> 3; int k = (f & 7) * 4;
        ra[q] = (k < K) ? *(const float4*)(A + (long)(ib + r) * M_ + k) : make_float4(0,0,0,0);
        rb[q] = (k < K) ? *(const float4*)(A + (long)(jb + r) * M_ + k) : make_float4(0,0,0,0);
    }
    #pragma unroll
    for (int q = 0; q < 4; q++) {
        int f = tid + q * GT; int r = f >> 3; int c = (f & 7) * 4;
        *(float4*)(sm + (long)r * APAD + c)           = ra[q];
        *(float4*)(sm + ATILE_F + (long)r * APAD + c) = rb[q];
    }
    __syncthreads();

    for (int i = 0; i < NC; i++) {
        if (i + 1 < NC) {
            const int k0 = (i + 1) * KCH;
            #pragma unroll
            for (int q = 0; q < 4; q++) {
                int f = tid + q * GT; int r = f >> 3; int k = k0 + (f & 7) * 4;
                ra[q] = (k < K) ? *(const float4*)(A + (long)(ib + r) * M_ + k) : make_float4(0,0,0,0);
                rb[q] = (k < K) ? *(const float4*)(A + (long)(jb + r) * M_ + k) : make_float4(0,0,0,0);
            }
        }
        const float* As = sm + (i & 1) * STAGE_F;
        const float* Bs = As + ATILE_F;
        #pragma unroll
        for (int ks = 0; ks < 4; ks++) {
            uint32_t ah[4][4], al[4][4];
            #pragma unroll
            for (int mf = 0; mf < 4; mf++) {
                int base = (wm * 64 + mf * 16 + gid) * APAD + ks * 8 + tig;
                split_tf32(As[base],                ah[mf][0], al[mf][0]);
                split_tf32(As[base + 8 * APAD],     ah[mf][1], al[mf][1]);
                split_tf32(As[base + 4],            ah[mf][2], al[mf][2]);
                split_tf32(As[base + 8 * APAD + 4], ah[mf][3], al[mf][3]);
            }
            uint32_t bh[4][2], bl[4][2];
            #pragma unroll
            for (int nf = 0; nf < 4; nf++) {
                int base = (wn * 32 + nf * 8 + gid) * APAD + ks * 8 + tig;
                split_tf32(Bs[base],     bh[nf][0], bl[nf][0]);
                split_tf32(Bs[base + 4], bh[nf][1], bl[nf][1]);
            }
            #pragma unroll
            for (int mf = 0; mf < 4; mf++)
                #pragma unroll
                for (int nf = 0; nf < 4; nf++) {
                    mma_tf32(acc[mf][nf], ah[mf], bh[nf]);
                    mma_tf32(acc[mf][nf], ah[mf], bl[nf]);
                    mma_tf32(acc[mf][nf], al[mf], bh[nf]);
                }
        }
        if (i + 1 < NC) {
            float* Ad = sm + ((i + 1) & 1) * STAGE_F;
            #pragma unroll
            for (int q = 0; q < 4; q++) {
                int f = tid + q * GT; int r = f >> 3; int c = (f & 7) * 4;
                *(float4*)(Ad + (long)r * APAD + c)           = ra[q];
                *(float4*)(Ad + ATILE_F + (long)r * APAD + c) = rb[q];
            }
        }
        __syncthreads();
    }

    const bool offdiag = (ib != jb);
    #pragma unroll
    for (int mf = 0; mf < 4; mf++) {
        const int row0 = ib + wm * 64 + mf * 16 + gid;
        float mi0 = meang[b * C_ + row0];
        float mi1 = meang[b * C_ + row0 + 8];
        #pragma unroll
        for (int nf = 0; nf < 4; nf++) {
            const int col0 = jb + wn * 32 + nf * 8 + tig * 2;
            float mj0 = meang[b * C_ + col0], mj1 = meang[b * C_ + col0 + 1];
            float c0 = acc[mf][nf][0] * covInvM - mi0 * mj0;
            float c1 = acc[mf][nf][1] * covInvM - mi0 * mj1;
            float c2 = acc[mf][nf][2] * covInvM - mi1 * mj0;
            float c3 = acc[mf][nf][3] * covInvM - mi1 * mj1;
            *(float2*)(C + (long)row0 * C_ + col0)       = make_float2(c0, c1);
            *(float2*)(C + (long)(row0 + 8) * C_ + col0) = make_float2(c2, c3);
            if (offdiag) {
                C[(long)col0 * C_ + row0]           = c0;
                C[(long)(col0 + 1) * C_ + row0]     = c1;
                C[(long)col0 * C_ + row0 + 8]       = c2;
                C[(long)(col0 + 1) * C_ + row0 + 8] = c3;
            }
        }
    }
}

// ---------------- per-row mean of x ----------------
__global__ void mean_kernel(const float* __restrict__ x, float* __restrict__ mean)
{
    int warp = (blockIdx.x * blockDim.x + threadIdx.x) >> 5;
    int lane = threadIdx.x & 31;
    if (warp >= B_*C_) return;
    const float* row = x + (long)warp * M_;
    float s = 0.f;
    for (int k = lane; k < M_; k += 32) s += row[k];
    #pragma unroll
    for (int off = 16; off; off >>= 1) s += __shfl_down_sync(0xffffffffu, s, off);
    if (lane == 0) mean[warp] = s * (1.0f / M_);
}

// ---------------- trace ----------------
__global__ void trace_kernel(const float* __restrict__ A,
                             float* __restrict__ itr, float* __restrict__ str)
{
    __shared__ float sh[512];
    const int b = blockIdx.x;
    const int i = threadIdx.x;
    sh[i] = A[(long)b * NSQ + (long)i * C_ + i];
    __syncthreads();
    for (int off = 256; off; off >>= 1) {
        if (i < off) sh[i] += sh[i + off];
        __syncthreads();
    }
    if (i == 0) { float t = sh[0]; itr[b] = 1.0f / t; str[b] = sqrtf(t); }
}

// ================= Newton-Schulz vector chain (4-CTA cluster per batch) =================
// Ysqrt/sqrt(tr) = T * W0..W4, W_k = 1.5I - 0.5 S_k, S_0 = T, S_{k+1} = S_k W_k^2.
// 122 matvecs; each split over 4 CTAs by output column; v exchanged via DSMEM.
__device__ __forceinline__ uint32_t smem_u32(const void* p) {
    uint32_t a;
    asm("{ .reg .u64 t; cvta.to.shared.u64 t, %1; cvt.u32.u64 %0, t; }" : "=r"(a) : "l"(p));
    return a;
}
__device__ __forceinline__ uint32_t mapa_u32(uint32_t laddr, uint32_t rank) {
    uint32_t r;
    asm volatile("mapa.shared::cluster.u32 %0, %1, %2;" : "=r"(r) : "r"(laddr), "r"(rank));
    return r;
}
__device__ __forceinline__ void st_cluster_f32(uint32_t addr, float v) {
    asm volatile("st.shared::cluster.f32 [%0], %1;" :: "r"(addr), "f"(v) : "memory");
}
__device__ __forceinline__ uint32_t cluster_rank() {
    uint32_t r;
    asm("mov.u32 %0, %%cluster_ctarank;" : "=r"(r));
    return r;
}
#define CLUSTER_SYNC() do { \
    asm volatile("barrier.cluster.arrive.aligned;" ::: "memory"); \
    asm volatile("barrier.cluster.wait.aligned;" ::: "memory"); \
} while (0)

struct Ctx {
    const float* Ab;     // batch matrix base (row-major 512x512, symmetric)
    float* v;            // smem double-buffered vector [2*512]
    float* pool;         // smem save stack [5*512]
    float* partial;      // smem [32*128]
    float  inv;
    int    tid;
    uint32_t rank;
    int    cur;
};

// v[nxt](full, all CTAs) <- inv * (v[cur]^T A); one cluster sync.
__device__ void do_matvec(Ctx& c)
{
    const int j4 = c.tid & 31;          // column group (4 cols) within our 128
    const int isec = c.tid >> 5;        // 0..31, 16 rows each
    const int nxt = c.cur ^ 1;
    const float* base = c.Ab + (long)isec * 16 * C_ + c.rank * 128 + j4 * 4;
    const float* vs = c.v + c.cur * 512 + isec * 16;
    float4 acc = make_float4(0.f, 0.f, 0.f, 0.f);
    #pragma unroll
    for (int ii = 0; ii < 16; ii++) {
        float s = vs[ii];
        float4 t = *(const float4*)(base + (long)ii * C_);
        acc.x = fmaf(s, t.x, acc.x);
        acc.y = fmaf(s, t.y, acc.y);
        acc.z = fmaf(s, t.z, acc.z);
        acc.w = fmaf(s, t.w, acc.w);
    }
    *(float4*)(c.partial + isec * 128 + j4 * 4) = acc;
    __syncthreads();
    if (c.tid < 128) {
        float s = 0.f;
        #pragma unroll
        for (int e = 0; e < 32; e++) s += c.partial[e * 128 + c.tid];
        s *= c.inv;
        uint32_t laddr = smem_u32(c.v + nxt * 512 + c.rank * 128 + c.tid);
        #pragma unroll
        for (uint32_t p = 0; p < 4; p++) st_cluster_f32(mapa_u32(laddr, p), s);
    }
    CLUSTER_SYNC();
    c.cur = nxt;
}

__device__ void applyS(int k, Ctx& c, int sp);

// v <- v * W_k = 1.5 v - 0.5 (v S_k)   (combine is local & identical in all CTAs)
__device__ void applyW(int k, Ctx& c, int sp)
{
    float* save = c.pool + sp * 512;
    if (c.tid < 512) save[c.tid] = c.v[c.cur * 512 + c.tid];
    __syncthreads();
    applyS(k, c, sp + 1);
    if (c.tid < 512) c.v[c.cur * 512 + c.tid] = 1.5f * save[c.tid] - 0.5f * c.v[c.cur * 512 + c.tid];
    __syncthreads();
}

__device__ void applyS(int k, Ctx& c, int sp)
{
    if (k == 0) { do_matvec(c); return; }
    applyS(k - 1, c, sp);
    applyW(k - 1, c, sp);
    applyW(k - 1, c, sp);
}

__global__ void __launch_bounds__(1024, 1) __cluster_dims__(4, 1, 1)
chain_kernel(const float* __restrict__ A, const float* __restrict__ itr,
             const float* __restrict__ str, float* __restrict__ cs)
{
    __shared__ float v[2 * 512];
    __shared__ float pool[5 * 512];
    __shared__ float partial[32 * 128];
    const int tid = threadIdx.x;
    const int b = blockIdx.x >> 2;

    Ctx c;
    c.Ab = A + (long)b * NSQ;
    c.v = v; c.pool = pool; c.partial = partial;
    c.inv = itr[b]; c.tid = tid; c.rank = cluster_rank(); c.cur = 0;

    if (tid < 512) v[tid] = 1.0f;
    __syncthreads();

    do_matvec(c);                 // u = 1^T * T
    for (int k = 0; k < 5; k++)   // u = u * W_k
        applyW(k, c, 0);

    if (c.rank == 0 && tid < 512)
        cs[b * C_ + tid] = c.v[c.cur * 512 + tid] * str[b] * (1.0f / C_);
}

// ---------------- out = cov_sum * x ----------------
__global__ void scale_kernel(const float* __restrict__ x,
                             const float* __restrict__ cs, float* __restrict__ out)
{
    long i4 = (long)blockIdx.x * blockDim.x + threadIdx.x;
    const long total4 = (long)B_ * C_ * M_ / 4;
    if (i4 >= total4) return;
    long e = i4 * 4;
    int bc = (int)(e / M_);
    float s = cs[bc];
    float4 v = *(const float4*)(x + e);
    v.x *= s; v.y *= s; v.z *= s; v.w *= s;
    *(float4*)(out + e) = v;
}

// ---------------- launcher ----------------
extern "C" void kernel_launch(void* const* d_in, const int* in_sizes, int n_in,
                              void* d_out, int out_size)
{
    const float* x = (const float*)d_in[0];
    float* out = (float*)d_out;

    float *A, *mean, *itr, *str, *cs;
    cudaGetSymbolAddress((void**)&A,    g_A);
    cudaGetSymbolAddress((void**)&mean, g_mean);
    cudaGetSymbolAddress((void**)&itr,  g_itr);
    cudaGetSymbolAddress((void**)&str,  g_str);
    cudaGetSymbolAddress((void**)&cs,   g_cs);

    cudaFuncSetAttribute(cov_gemm, cudaFuncAttributeMaxDynamicSharedMemorySize, GEMM_SMEM);

    // 1) row means
    mean_kernel<<<(B_*C_ + 7) / 8, 256>>>(x, mean);

    // 2) covariance (symmetric: 10 upper-tri tiles, write both halves)
    cov_gemm<<<dim3(10, 1, B_), GT, GEMM_SMEM>>>(x, A, mean);

    // 3) trace scalars
    trace_kernel<<<B_, 512>>>(A, itr, str);

    // 4) Newton-Schulz chain: 122 matvecs, 4-CTA cluster per batch
    chain_kernel<<<B_ * 4, 1024>>>(A, itr, str, cs);

    // 5) out = cov_sum[b][c] * x
    const long total4 = (long)B_ * C_ * M_ / 4;
    scale_kernel<<<(int)((total4 + 255) / 256), 256>>>(x, cs, out);

    (void)in_sizes; (void)n_in; (void)out_size;
}